// round 15
// baseline (speedup 1.0000x reference)
#include <cuda_runtime.h>

#define KPTS    16384
#define NATOMS  1024
#define NB      16
#define NSRC    17      // source 0 = C, sources 1..16 = C1[b]
#define NC      5       // cells per axis (h = 2.0)
#define NCELLS  125
#define DCAP    640     // max dom points per cell
#define SEGCAP  256     // per-warp dom segment capacity (mean ~33)
#define SCAP    256     // pruned atom capacity per cell (mean ~92 @ R=1.4)
#define NPAIR   (SCAP / 2)

// L = inv2s * log2(e) = 2*pi * 1.4426950408889634
#define LCONST  9.064720283654388f
// prune cutoff: atoms farther than RCUT from the cell cube are dropped.
// worst-case truncation ~2e-5 relative per theta (tolerance 1e-3).
#define RCUT2   1.96f   // 1.4^2

typedef unsigned long long u64;

// static scratch (no allocations allowed)
__device__ ulonglong2 g_pairsA[NSRC * NCELLS * NPAIR];  // (x0,x1),(y0,y1)
__device__ ulonglong2 g_pairsB[NSRC * NCELLS * NPAIR];  // (z0,z1),(w0,w1)
__device__ int        g_pcount[NSRC * NCELLS];          // pair counts
__device__ float4     g_kc[NCELLS * DCAP];              // stitched kcoefs
__device__ float      g_t0c[NCELLS * DCAP];             // theta0 in stitched order
__device__ int        g_dcountc[NCELLS];
__device__ float      g_part[NB * NCELLS];              // per (b, cell) dot partials
__device__ int        g_ctr[NB];                        // completion counters (self-resetting)

__device__ __forceinline__ int cell_of(float x, float y, float z) {
    int cx = min(NC - 1, max(0, (int)(x * 0.5f)));
    int cy = min(NC - 1, max(0, (int)(y * 0.5f)));
    int cz = min(NC - 1, max(0, (int)(z * 0.5f)));
    return (cz * NC + cy) * NC + cx;
}

// ---- packed f32x2 helpers --------------------------------------------------
__device__ __forceinline__ u64 pk2(float lo, float hi) {
    u64 r; asm("mov.b64 %0, {%1, %2};" : "=l"(r) : "f"(lo), "f"(hi)); return r;
}
__device__ __forceinline__ void upk2(u64 v, float& lo, float& hi) {
    asm("mov.b64 {%0, %1}, %2;" : "=f"(lo), "=f"(hi) : "l"(v));
}
__device__ __forceinline__ u64 fma2(u64 a, u64 b, u64 c) {
    u64 r; asm("fma.rn.f32x2 %0, %1, %2, %3;" : "=l"(r) : "l"(a), "l"(b), "l"(c)); return r;
}
__device__ __forceinline__ u64 add2(u64 a, u64 b) {
    u64 r; asm("add.rn.f32x2 %0, %1, %2;" : "=l"(r) : "l"(a), "l"(b)); return r;
}
__device__ __forceinline__ float ex2(float a) {
    float e; asm("ex2.approx.ftz.f32 %0, %1;" : "=f"(e) : "f"(a)); return e;
}
__device__ __forceinline__ float ldcg(const float* p) {
    float v; asm volatile("ld.global.cg.f32 %0, [%1];" : "=f"(v) : "l"(p)); return v;
}

// inner f32x2 theta accumulator over a pair list in smem ----------------------
__device__ __forceinline__ float theta_point(const float4 kc,
                                             const ulonglong2* __restrict__ sA,
                                             const ulonglong2* __restrict__ sB,
                                             int npairs) {
    const u64 kx2 = pk2(kc.x, kc.x);
    const u64 ky2 = pk2(kc.y, kc.y);
    const u64 kz2 = pk2(kc.z, kc.z);
    const u64 kw2 = pk2(kc.w, kc.w);
    u64 acc = 0ull;
    #pragma unroll 4
    for (int jp = 0; jp < npairs; ++jp) {
        ulonglong2 A = sA[jp];
        ulonglong2 B = sB[jp];
        u64 t = add2(B.y, kw2);
        t = fma2(kz2, B.x, t);
        t = fma2(ky2, A.y, t);
        t = fma2(kx2, A.x, t);
        float lo, hi; upk2(t, lo, hi);
        acc = add2(acc, pk2(ex2(lo), ex2(hi)));
    }
    float a0, a1; upk2(acc, a0, a1);
    return a0 + a1;
}

// ---------------------------------------------------------------------------
// prep: grid (125, 17) x 128 threads. Per (cell, source):
//   load ALL 1024 raw atoms of the source to smem, prune to atoms within
//   RCUT of the home cell cube (dropped terms bounded above), transform to
//   coefficients, pack f32x2 pairs -> global (and smem).
// s==0 blocks additionally bin the cell's dom points THEMSELVES: warp w
//   scans dom quarter w, ballot-compacts in-cell points (kcoef on the fly)
//   into a per-warp smem segment (reusing the satoms buffer), concatenates
//   segments in warp order (deterministic stitched order), writes g_kc and
//   computes theta0 into g_t0c.
// Deterministic: prune & scan preserve index order; theta0 inner order fixed.
// ---------------------------------------------------------------------------
__global__ void __launch_bounds__(128) prep_kernel(const float* __restrict__ C1,
                                                   const float* __restrict__ C,
                                                   const float* __restrict__ dom) {
    __shared__ float4     satoms[NATOMS];     // atoms; later reused as dom segments
    __shared__ ulonglong2 sA[NPAIR], sB[NPAIR];
    __shared__ int        sNk;
    const int cell = blockIdx.x;
    const int s    = blockIdx.y;
    const int tid  = threadIdx.x;
    const int lane = tid & 31;
    const int w    = tid >> 5;                // warp 0..3
    const int cx = cell % NC, cy = (cell / NC) % NC, cz = cell / (NC * NC);

    const float* src = (s == 0) ? C : (C1 + (size_t)(s - 1) * NATOMS * 3);
    for (int i = tid; i < NATOMS; i += 128) {
        satoms[i] = make_float4(src[i * 3 + 0], src[i * 3 + 1], src[i * 3 + 2], 0.f);
    }
    __syncthreads();

    // prune (warp 0, deterministic in-place ballot compaction over all atoms)
    if (tid < 32) {
        const float lox = cx * 2.f, hix = lox + 2.f;
        const float loy = cy * 2.f, hiy = loy + 2.f;
        const float loz = cz * 2.f, hiz = loz + 2.f;
        int nk = 0;
        for (int i0 = 0; i0 < NATOMS; i0 += 32) {
            int i = i0 + lane;
            float4 a = satoms[i];
            float dx = fmaxf(fmaxf(lox - a.x, a.x - hix), 0.f);
            float dy = fmaxf(fmaxf(loy - a.y, a.y - hiy), 0.f);
            float dz = fmaxf(fmaxf(loz - a.z, a.z - hiz), 0.f);
            bool keep = fmaf(dx, dx, fmaf(dy, dy, dz * dz)) <= RCUT2;
            unsigned m = __ballot_sync(0xffffffffu, keep);
            __syncwarp();
            if (keep) {
                int pos = nk + __popc(m & ((1u << lane) - 1u));
                if (pos < SCAP) satoms[pos] = a;
            }
            nk += __popc(m);
        }
        if (lane == 0) sNk = min(nk, SCAP);
    }
    __syncthreads();

    const int nk     = sNk;
    const int npairs = (nk + 1) >> 1;

    // pack coefficient pairs (transform raw -> (2Lx,2Ly,2Lz,-L|x|^2) here)
    ulonglong2* gA = g_pairsA + (size_t)(s * NCELLS + cell) * NPAIR;
    ulonglong2* gB = g_pairsB + (size_t)(s * NCELLS + cell) * NPAIR;
    for (int jp = tid; jp < npairs; jp += 128) {
        float4 a = satoms[2 * jp];
        float4 ac = make_float4(2.f * LCONST * a.x, 2.f * LCONST * a.y,
                                2.f * LCONST * a.z,
                                -LCONST * (a.x * a.x + a.y * a.y + a.z * a.z));
        float4 bc;
        if (2 * jp + 1 < nk) {
            float4 b = satoms[2 * jp + 1];
            bc = make_float4(2.f * LCONST * b.x, 2.f * LCONST * b.y,
                             2.f * LCONST * b.z,
                             -LCONST * (b.x * b.x + b.y * b.y + b.z * b.z));
        } else {
            bc = make_float4(0.f, 0.f, 0.f, -1e30f);   // pad -> exp2 flushes to 0
        }
        ulonglong2 pa = make_ulonglong2(pk2(ac.x, bc.x), pk2(ac.y, bc.y));
        ulonglong2 pb = make_ulonglong2(pk2(ac.z, bc.z), pk2(ac.w, bc.w));
        gA[jp] = pa;  gB[jp] = pb;
        sA[jp] = pa;  sB[jp] = pb;
    }
    if (tid == 0) g_pcount[s * NCELLS + cell] = npairs;

    if (s == 0) {
        // ---- dom binning for this cell (warp-sliced scan, deterministic) --
        __shared__ int wcntD[4], wbase[5];
        __syncthreads();                       // pack done -> satoms reusable
        float4* seg = satoms;                  // seg[w][SEGCAP]

        int cnt = 0;
        const int beg = w * (KPTS / 4), end = beg + (KPTS / 4);
        for (int i0 = beg; i0 < end; i0 += 32) {
            int i = i0 + lane;
            float x = dom[i * 3 + 0];
            float y = dom[i * 3 + 1];
            float z = dom[i * 3 + 2];
            bool in = (cell_of(x, y, z) == cell);
            unsigned m = __ballot_sync(0xffffffffu, in);
            if (in) {
                int pos = cnt + __popc(m & ((1u << lane) - 1u));
                if (pos < SEGCAP)
                    seg[w * SEGCAP + pos] =
                        make_float4(x, y, z, -LCONST * (x * x + y * y + z * z));
            }
            cnt += __popc(m);
        }
        if (lane == 0) wcntD[w] = min(cnt, SEGCAP);
        __syncthreads();
        if (tid == 0) {
            int a = 0;
            #pragma unroll
            for (int i = 0; i < 4; ++i) { wbase[i] = a; a += wcntD[i]; }
            wbase[4] = a;
            g_dcountc[cell] = min(a, DCAP);
        }
        __syncthreads();

        // theta0 + stitched outputs, warp-local (fixed order)
        const int nw = wcntD[w], base = wbase[w];
        for (int j = lane; j < nw; j += 32) {
            int pos = base + j;
            if (pos < DCAP) {
                float4 kc = seg[w * SEGCAP + j];
                g_kc[cell * DCAP + pos]  = kc;
                g_t0c[cell * DCAP + pos] = theta_point(kc, sA, sB, npairs);
            }
        }
    }
}

// ---------------------------------------------------------------------------
// thetaB: grid (125, 16) x 160 threads, s = b+1. Computes theta_b per point,
// multiplies by theta0 (stitched order) immediately, block-reduces to one
// partial per (b, cell). The LAST block per b (elected by atomic counter)
// folds all 125 partials IN FIXED ORDER and writes out[b], then resets the
// counter for graph replay. Deterministic: the atomic elects only WHO folds;
// the fold order is fixed.
// scale = A*V/sqrt(n1*n2) = 8 * (1000/16384) / 1024.
// ---------------------------------------------------------------------------
__global__ void __launch_bounds__(160) thetaB_kernel(float* __restrict__ out) {
    __shared__ ulonglong2 sA[NPAIR];
    __shared__ ulonglong2 sB[NPAIR];
    __shared__ float      red[5];
    __shared__ int        sIsLast;
    const int cell = blockIdx.x;
    const int b    = blockIdx.y;
    const int s    = b + 1;
    const int tid  = threadIdx.x;
    const int lane = tid & 31;
    const int w    = tid >> 5;

    const int npairs = g_pcount[s * NCELLS + cell];
    const int npts   = g_dcountc[cell];
    const ulonglong2* gA = g_pairsA + (size_t)(s * NCELLS + cell) * NPAIR;
    const ulonglong2* gB = g_pairsB + (size_t)(s * NCELLS + cell) * NPAIR;
    for (int i = tid; i < npairs; i += 160) {
        sA[i] = gA[i];
        sB[i] = gB[i];
    }
    __syncthreads();

    float pdot = 0.f;
    for (int p = tid; p < npts; p += 160) {
        float tb = theta_point(g_kc[cell * DCAP + p], sA, sB, npairs);
        pdot += tb * g_t0c[cell * DCAP + p];
    }
    #pragma unroll
    for (int st = 16; st > 0; st >>= 1)
        pdot += __shfl_down_sync(0xffffffffu, pdot, st);
    if (lane == 0) red[w] = pdot;
    __syncthreads();
    if (tid == 0) {
        float a = 0.f;
        #pragma unroll
        for (int i = 0; i < 5; ++i) a += red[i];
        g_part[b * NCELLS + cell] = a;
        __threadfence();
        int old = atomicAdd(&g_ctr[b], 1);
        sIsLast = (old == NCELLS - 1);
    }
    __syncthreads();

    if (sIsLast) {
        __threadfence();
        // fold 125 partials in fixed order (warps 0..3, lanes ascending)
        float v = (tid < NCELLS) ? ldcg(&g_part[b * NCELLS + tid]) : 0.f;
        #pragma unroll
        for (int st = 16; st > 0; st >>= 1)
            v += __shfl_down_sync(0xffffffffu, v, st);
        if (lane == 0) red[w] = v;
        __syncthreads();
        if (tid == 0) {
            float a = ((red[0] + red[1]) + (red[2] + red[3])) + red[4];
            float dot = 4.76837158203125e-4f * a;
            dot = fminf(fmaxf(dot, 0.f), 1.f);
            out[b] = 1.f - dot;
            g_ctr[b] = 0;                    // reset for graph replay
        }
    }
}

extern "C" void kernel_launch(void* const* d_in, const int* in_sizes, int n_in,
                              void* d_out, int out_size) {
    const float* C1  = (const float*)d_in[0];   // (16, 1024, 3)
    const float* C   = (const float*)d_in[1];   // (1024, 3)
    const float* dom = (const float*)d_in[2];   // (16384, 3)

    prep_kernel<<<dim3(NCELLS, NSRC), 128>>>(C1, C, dom);
    thetaB_kernel<<<dim3(NCELLS, NB), 160>>>((float*)d_out);
}

// round 16
// speedup vs baseline: 1.3559x; 1.3559x over previous
#include <cuda_runtime.h>

#define KPTS    16384
#define NATOMS  1024
#define NB      16
#define NSRC    17      // source 0 = C, sources 1..16 = C1[b]
#define NC      5       // cells per axis (h = 2.0)
#define NCELLS  125
#define NSLICE  16      // dom binning slices (1024 points each)
#define SLCAP   40      // dom points per (cell, slice) capacity (mean 8.2)
#define DCAP    640     // max dom points per cell (16*40)
#define SCAP    256     // pruned atom capacity per cell (mean ~92 @ R=1.4)
#define NPAIR   (SCAP / 2)

// L = inv2s * log2(e) = 2*pi * 1.4426950408889634
#define LCONST  9.064720283654388f
// prune cutoff: atoms farther than RCUT from the cell cube are dropped.
// worst-case truncation ~2e-5 relative per theta (tolerance 1e-3).
#define RCUT2   1.96f   // 1.4^2

typedef unsigned long long u64;

// static scratch (no allocations allowed)
__device__ int        g_dslice[NCELLS * NSLICE * SLCAP];
__device__ int        g_dcnt2[NCELLS * NSLICE];
__device__ float4     g_kcoef[KPTS];
__device__ ulonglong2 g_pairsA[NSRC * NCELLS * NPAIR];  // (x0,x1),(y0,y1)
__device__ ulonglong2 g_pairsB[NSRC * NCELLS * NPAIR];  // (z0,z1),(w0,w1)
__device__ int        g_pcount[NSRC * NCELLS];          // pair counts
__device__ float4     g_kc[NCELLS * DCAP];              // stitched kcoefs
__device__ float      g_t0c[NCELLS * DCAP];             // theta0 in stitched order
__device__ int        g_dcountc[NCELLS];
__device__ float      g_part[NB * NCELLS];              // per (b, cell) dot partials
__device__ int        g_ctr;                            // completion counter (self-resetting)

__device__ __forceinline__ int cell_of(float x, float y, float z) {
    int cx = min(NC - 1, max(0, (int)(x * 0.5f)));
    int cy = min(NC - 1, max(0, (int)(y * 0.5f)));
    int cz = min(NC - 1, max(0, (int)(z * 0.5f)));
    return (cz * NC + cy) * NC + cx;
}

// ---- packed f32x2 helpers --------------------------------------------------
__device__ __forceinline__ u64 pk2(float lo, float hi) {
    u64 r; asm("mov.b64 %0, {%1, %2};" : "=l"(r) : "f"(lo), "f"(hi)); return r;
}
__device__ __forceinline__ void upk2(u64 v, float& lo, float& hi) {
    asm("mov.b64 {%0, %1}, %2;" : "=f"(lo), "=f"(hi) : "l"(v));
}
__device__ __forceinline__ u64 fma2(u64 a, u64 b, u64 c) {
    u64 r; asm("fma.rn.f32x2 %0, %1, %2, %3;" : "=l"(r) : "l"(a), "l"(b), "l"(c)); return r;
}
__device__ __forceinline__ u64 add2(u64 a, u64 b) {
    u64 r; asm("add.rn.f32x2 %0, %1, %2;" : "=l"(r) : "l"(a), "l"(b)); return r;
}
__device__ __forceinline__ float ex2(float a) {
    float e; asm("ex2.approx.ftz.f32 %0, %1;" : "=f"(e) : "f"(a)); return e;
}
__device__ __forceinline__ float ldcg(const float* p) {
    float v; asm volatile("ld.global.cg.f32 %0, [%1];" : "=f"(v) : "l"(p)); return v;
}

// inner f32x2 theta accumulator over a pair list in smem ----------------------
__device__ __forceinline__ float theta_point(const float4 kc,
                                             const ulonglong2* __restrict__ sA,
                                             const ulonglong2* __restrict__ sB,
                                             int npairs) {
    const u64 kx2 = pk2(kc.x, kc.x);
    const u64 ky2 = pk2(kc.y, kc.y);
    const u64 kz2 = pk2(kc.z, kc.z);
    const u64 kw2 = pk2(kc.w, kc.w);
    u64 acc = 0ull;
    #pragma unroll 4
    for (int jp = 0; jp < npairs; ++jp) {
        ulonglong2 A = sA[jp];
        ulonglong2 B = sB[jp];
        u64 t = add2(B.y, kw2);
        t = fma2(kz2, B.x, t);
        t = fma2(ky2, A.y, t);
        t = fma2(kx2, A.x, t);
        float lo, hi; upk2(t, lo, hi);
        acc = add2(acc, pk2(ex2(lo), ex2(hi)));
    }
    float a0, a1; upk2(acc, a0, a1);
    return a0 + a1;
}

// ---------------------------------------------------------------------------
// prep1: 16 blocks x 1024 threads — DETERMINISTIC dom binning by slice
// (match_any per-warp counts + parallel across-warp prefix; slot = warp base
// + intra-warp lane rank -> stitched order is run-stable, which the fused dot
// requires). Also writes per-point kcoef (kx, ky, kz, -L*|k|^2).
// ---------------------------------------------------------------------------
__global__ void __launch_bounds__(1024) prep1_kernel(const float* __restrict__ dom) {
    __shared__ int wcnt[32 * 128];           // [warp][cell]
    const int tid = threadIdx.x;
    const int bid = blockIdx.x;
    const int lane = tid & 31;
    const int w    = tid >> 5;

    #pragma unroll
    for (int i = 0; i < 4; ++i) wcnt[tid + i * 1024] = 0;

    const int k = bid * 1024 + tid;
    const float x = dom[k * 3 + 0];
    const float y = dom[k * 3 + 1];
    const float z = dom[k * 3 + 2];
    g_kcoef[k] = make_float4(x, y, z, -LCONST * (x * x + y * y + z * z));
    const int c = cell_of(x, y, z);
    __syncthreads();

    unsigned mm  = __match_any_sync(0xffffffffu, c);
    int     rank = __popc(mm & ((1u << lane) - 1u));
    if (rank == 0) wcnt[w * 128 + c] = __popc(mm);
    __syncthreads();

    if (tid < NCELLS) {
        int acc = 0;
        #pragma unroll
        for (int ww = 0; ww < 32; ++ww) {
            int v = wcnt[ww * 128 + tid];
            wcnt[ww * 128 + tid] = acc;       // exclusive warp base
            acc += v;
        }
        g_dcnt2[tid * NSLICE + bid] = min(acc, SLCAP);
    }
    __syncthreads();

    int slot = wcnt[w * 128 + c] + rank;
    if (slot < SLCAP) g_dslice[(c * NSLICE + bid) * SLCAP + slot] = k;
}

// ---------------------------------------------------------------------------
// prep2: grid (125, 17) x 128 threads. Per (cell, source):
//   load ALL 1024 raw atoms of the source to smem, prune to atoms within
//   RCUT of the home cell cube (dropped terms bounded above), transform to
//   coefficients, pack f32x2 pairs -> global (and smem).
// s==0 blocks additionally stitch the cell's dom points into contiguous
//   (kcoef) arrays and compute theta0 into g_t0c.
// Deterministic: prune preserves atom index order; theta0 inner order fixed.
// ---------------------------------------------------------------------------
__global__ void __launch_bounds__(128) prep2_kernel(const float* __restrict__ C1,
                                                    const float* __restrict__ C) {
    __shared__ float4     satoms[NATOMS];     // raw coords, then compacted
    __shared__ ulonglong2 sA[NPAIR], sB[NPAIR];
    __shared__ float4     skc[DCAP];
    __shared__ int        sNk, sNpts;
    const int cell = blockIdx.x;
    const int s    = blockIdx.y;
    const int tid  = threadIdx.x;
    const int lane = tid & 31;
    const int cx = cell % NC, cy = (cell / NC) % NC, cz = cell / (NC * NC);

    const float* src = (s == 0) ? C : (C1 + (size_t)(s - 1) * NATOMS * 3);
    for (int i = tid; i < NATOMS; i += 128) {
        satoms[i] = make_float4(src[i * 3 + 0], src[i * 3 + 1], src[i * 3 + 2], 0.f);
    }
    __syncthreads();

    // prune (warp 0, deterministic in-place ballot compaction over all atoms)
    if (tid < 32) {
        const float lox = cx * 2.f, hix = lox + 2.f;
        const float loy = cy * 2.f, hiy = loy + 2.f;
        const float loz = cz * 2.f, hiz = loz + 2.f;
        int nk = 0;
        for (int i0 = 0; i0 < NATOMS; i0 += 32) {
            int i = i0 + lane;
            float4 a = satoms[i];
            float dx = fmaxf(fmaxf(lox - a.x, a.x - hix), 0.f);
            float dy = fmaxf(fmaxf(loy - a.y, a.y - hiy), 0.f);
            float dz = fmaxf(fmaxf(loz - a.z, a.z - hiz), 0.f);
            bool keep = fmaf(dx, dx, fmaf(dy, dy, dz * dz)) <= RCUT2;
            unsigned m = __ballot_sync(0xffffffffu, keep);
            __syncwarp();
            if (keep) {
                int pos = nk + __popc(m & ((1u << lane) - 1u));
                if (pos < SCAP) satoms[pos] = a;
            }
            nk += __popc(m);
        }
        if (lane == 0) sNk = min(nk, SCAP);
    }
    __syncthreads();

    const int nk     = sNk;
    const int npairs = (nk + 1) >> 1;

    // pack coefficient pairs (transform raw -> (2Lx,2Ly,2Lz,-L|x|^2) here)
    ulonglong2* gA = g_pairsA + (size_t)(s * NCELLS + cell) * NPAIR;
    ulonglong2* gB = g_pairsB + (size_t)(s * NCELLS + cell) * NPAIR;
    for (int jp = tid; jp < npairs; jp += 128) {
        float4 a = satoms[2 * jp];
        float4 ac = make_float4(2.f * LCONST * a.x, 2.f * LCONST * a.y,
                                2.f * LCONST * a.z,
                                -LCONST * (a.x * a.x + a.y * a.y + a.z * a.z));
        float4 bc;
        if (2 * jp + 1 < nk) {
            float4 b = satoms[2 * jp + 1];
            bc = make_float4(2.f * LCONST * b.x, 2.f * LCONST * b.y,
                             2.f * LCONST * b.z,
                             -LCONST * (b.x * b.x + b.y * b.y + b.z * b.z));
        } else {
            bc = make_float4(0.f, 0.f, 0.f, -1e30f);   // pad -> exp2 flushes to 0
        }
        ulonglong2 pa = make_ulonglong2(pk2(ac.x, bc.x), pk2(ac.y, bc.y));
        ulonglong2 pb = make_ulonglong2(pk2(ac.z, bc.z), pk2(ac.w, bc.w));
        gA[jp] = pa;  gB[jp] = pb;
        sA[jp] = pa;  sB[jp] = pb;
    }
    if (tid == 0) g_pcount[s * NCELLS + cell] = npairs;

    if (s == 0) {
        // stitch dom points (deterministic order) into smem + global
        __shared__ int scnt16[NSLICE], soff16[NSLICE + 1];
        if (tid < NSLICE) scnt16[tid] = g_dcnt2[cell * NSLICE + tid];
        __syncthreads();
        if (tid == 0) {
            int a = 0;
            #pragma unroll
            for (int i = 0; i < NSLICE; ++i) { soff16[i] = a; a += scnt16[i]; }
            soff16[NSLICE] = a;
            g_dcountc[cell] = a;
            sNpts = a;
        }
        __syncthreads();
        for (int idx = tid; idx < NSLICE * SLCAP; idx += 128) {
            int sl = idx / SLCAP, j = idx % SLCAP;
            if (j < scnt16[sl]) {
                int k = g_dslice[(cell * NSLICE + sl) * SLCAP + j];
                int pos = soff16[sl] + j;
                float4 kc = g_kcoef[k];
                skc[pos] = kc;
                g_kc[cell * DCAP + pos] = kc;
            }
        }
        __syncthreads();

        // theta0 for this cell's points (fixed order)
        const int npts = sNpts;
        for (int p = tid; p < npts; p += 128) {
            g_t0c[cell * DCAP + p] = theta_point(skc[p], sA, sB, npairs);
        }
    }
}

// ---------------------------------------------------------------------------
// thetaB: grid (125, 4) x 128 threads. WARP w owns b = 4*blockIdx.y + w.
// Block loads the cell's points + theta0 into smem once; each warp loads its
// own pair list into its smem slot (inner loop stays warp-uniform -> LDS
// broadcast). Warp computes sum_p theta_b(p)*theta0(p) over the cell, shuffle
// -reduces, writes g_part[b][cell]. The LAST of the 500 blocks (elected by a
// counter) folds all 16x125 partials IN FIXED ORDER and writes out, then
// resets the counter for graph replay.
// scale = A*V/sqrt(n1*n2) = 8 * (1000/16384) / 1024.
// ---------------------------------------------------------------------------
__global__ void __launch_bounds__(128) thetaB_kernel(float* __restrict__ out) {
    __shared__ ulonglong2 sA[4][NPAIR];
    __shared__ ulonglong2 sB[4][NPAIR];
    __shared__ float4     skc[DCAP];
    __shared__ float      st0[DCAP];
    __shared__ int        sIsLast;
    const int cell = blockIdx.x;
    const int tid  = threadIdx.x;
    const int lane = tid & 31;
    const int w    = tid >> 5;
    const int b    = blockIdx.y * 4 + w;    // 0..15
    const int s    = b + 1;

    const int npts = g_dcountc[cell];
    for (int p = tid; p < npts; p += 128) {
        skc[p] = g_kc[cell * DCAP + p];
        st0[p] = g_t0c[cell * DCAP + p];
    }
    const int npairs = g_pcount[s * NCELLS + cell];
    const ulonglong2* gA = g_pairsA + (size_t)(s * NCELLS + cell) * NPAIR;
    const ulonglong2* gB = g_pairsB + (size_t)(s * NCELLS + cell) * NPAIR;
    for (int i = lane; i < npairs; i += 32) {
        sA[w][i] = gA[i];
        sB[w][i] = gB[i];
    }
    __syncthreads();

    float pdot = 0.f;
    for (int p = lane; p < npts; p += 32)
        pdot += theta_point(skc[p], sA[w], sB[w], npairs) * st0[p];
    #pragma unroll
    for (int st = 16; st > 0; st >>= 1)
        pdot += __shfl_down_sync(0xffffffffu, pdot, st);
    if (lane == 0) {
        g_part[b * NCELLS + cell] = pdot;
        __threadfence();
    }
    __syncthreads();
    if (tid == 0) {
        int old = atomicAdd(&g_ctr, 1);
        sIsLast = (old == NCELLS * 4 - 1);
    }
    __syncthreads();

    if (sIsLast) {
        __threadfence();
        // warp w folds b = w, w+4, w+8, w+12 — fixed strided order per b
        for (int bb = w; bb < NB; bb += 4) {
            float v = 0.f;
            for (int c = lane; c < NCELLS; c += 32)
                v += ldcg(&g_part[bb * NCELLS + c]);
            #pragma unroll
            for (int st = 16; st > 0; st >>= 1)
                v += __shfl_down_sync(0xffffffffu, v, st);
            if (lane == 0) {
                float dot = 4.76837158203125e-4f * v;
                dot = fminf(fmaxf(dot, 0.f), 1.f);
                out[bb] = 1.f - dot;
            }
        }
        if (tid == 0) g_ctr = 0;            // reset for graph replay
    }
}

extern "C" void kernel_launch(void* const* d_in, const int* in_sizes, int n_in,
                              void* d_out, int out_size) {
    const float* C1  = (const float*)d_in[0];   // (16, 1024, 3)
    const float* C   = (const float*)d_in[1];   // (1024, 3)
    const float* dom = (const float*)d_in[2];   // (16384, 3)

    prep1_kernel<<<NSLICE, 1024>>>(dom);
    prep2_kernel<<<dim3(NCELLS, NSRC), 128>>>(C1, C);
    thetaB_kernel<<<dim3(NCELLS, 4), 128>>>((float*)d_out);
}

// round 17
// speedup vs baseline: 1.6169x; 1.1925x over previous
#include <cuda_runtime.h>

#define KPTS    16384
#define NATOMS  1024
#define NB      16
#define NSRC    17      // source 0 = C, sources 1..16 = C1[b]
#define NC      5       // cells per axis (h = 2.0)
#define NCELLS  125
#define NSLICE  32      // dom binning slices (512 points each)
#define SLCAP   28      // dom points per (cell, slice) capacity (mean 4.1)
#define DCAP    640     // max dom points per cell
#define SCAP    256     // pruned atom capacity per cell (mean ~92 @ R=1.4)
#define NPAIR   (SCAP / 2)

// L = inv2s * log2(e) = 2*pi * 1.4426950408889634
#define LCONST  9.064720283654388f
// prune cutoff: atoms farther than RCUT from the cell cube are dropped.
// worst-case truncation ~2e-5 relative per theta (tolerance 1e-3).
#define RCUT2   1.96f   // 1.4^2

typedef unsigned long long u64;

// static scratch (no allocations allowed)
__device__ int        g_dslice[NCELLS * NSLICE * SLCAP];
__device__ int        g_dcnt2[NCELLS * NSLICE];
__device__ float4     g_kcoef[KPTS];
__device__ ulonglong2 g_pairsA[NSRC * NCELLS * NPAIR];  // (x0,x1),(y0,y1)
__device__ ulonglong2 g_pairsB[NSRC * NCELLS * NPAIR];  // (z0,z1),(w0,w1)
__device__ int        g_pcount[NSRC * NCELLS];          // pair counts
__device__ float4     g_kc[NCELLS * DCAP];              // stitched kcoefs
__device__ float      g_t0c[NCELLS * DCAP];             // theta0 in stitched order
__device__ int        g_dcountc[NCELLS];
__device__ float      g_part[NB * NCELLS];              // per (b, cell) dot partials
__device__ int        g_ctr[NB];                        // completion counters (self-resetting)

__device__ __forceinline__ int cell_of(float x, float y, float z) {
    int cx = min(NC - 1, max(0, (int)(x * 0.5f)));
    int cy = min(NC - 1, max(0, (int)(y * 0.5f)));
    int cz = min(NC - 1, max(0, (int)(z * 0.5f)));
    return (cz * NC + cy) * NC + cx;
}

// ---- packed f32x2 helpers --------------------------------------------------
__device__ __forceinline__ u64 pk2(float lo, float hi) {
    u64 r; asm("mov.b64 %0, {%1, %2};" : "=l"(r) : "f"(lo), "f"(hi)); return r;
}
__device__ __forceinline__ void upk2(u64 v, float& lo, float& hi) {
    asm("mov.b64 {%0, %1}, %2;" : "=f"(lo), "=f"(hi) : "l"(v));
}
__device__ __forceinline__ u64 fma2(u64 a, u64 b, u64 c) {
    u64 r; asm("fma.rn.f32x2 %0, %1, %2, %3;" : "=l"(r) : "l"(a), "l"(b), "l"(c)); return r;
}
__device__ __forceinline__ u64 add2(u64 a, u64 b) {
    u64 r; asm("add.rn.f32x2 %0, %1, %2;" : "=l"(r) : "l"(a), "l"(b)); return r;
}
__device__ __forceinline__ float ex2(float a) {
    float e; asm("ex2.approx.ftz.f32 %0, %1;" : "=f"(e) : "f"(a)); return e;
}
__device__ __forceinline__ float ldcg(const float* p) {
    float v; asm volatile("ld.global.cg.f32 %0, [%1];" : "=f"(v) : "l"(p)); return v;
}

// inner f32x2 theta accumulator over a pair list in smem ----------------------
__device__ __forceinline__ float theta_point(const float4 kc,
                                             const ulonglong2* __restrict__ sA,
                                             const ulonglong2* __restrict__ sB,
                                             int npairs) {
    const u64 kx2 = pk2(kc.x, kc.x);
    const u64 ky2 = pk2(kc.y, kc.y);
    const u64 kz2 = pk2(kc.z, kc.z);
    const u64 kw2 = pk2(kc.w, kc.w);
    u64 acc = 0ull;
    #pragma unroll 4
    for (int jp = 0; jp < npairs; ++jp) {
        ulonglong2 A = sA[jp];
        ulonglong2 B = sB[jp];
        u64 t = add2(B.y, kw2);
        t = fma2(kz2, B.x, t);
        t = fma2(ky2, A.y, t);
        t = fma2(kx2, A.x, t);
        float lo, hi; upk2(t, lo, hi);
        acc = add2(acc, pk2(ex2(lo), ex2(hi)));
    }
    float a0, a1; upk2(acc, a0, a1);
    return a0 + a1;
}

// ---------------------------------------------------------------------------
// prep1: 32 blocks x 512 threads — DETERMINISTIC dom binning by slice
// (match_any per-warp counts + parallel across-warp prefix; slot = warp base
// + intra-warp lane rank -> stitched order is run-stable, which the fused dot
// requires). Also writes per-point kcoef (kx, ky, kz, -L*|k|^2).
// 32 blocks (vs 16) double SM coverage for the cold first-launch loads and
// halve the per-cell across-warp prefix chain (16 steps).
// ---------------------------------------------------------------------------
__global__ void __launch_bounds__(512) prep1_kernel(const float* __restrict__ dom) {
    __shared__ int wcnt[16 * 128];           // [warp][cell]
    const int tid = threadIdx.x;
    const int bid = blockIdx.x;
    const int lane = tid & 31;
    const int w    = tid >> 5;               // 0..15

    #pragma unroll
    for (int i = 0; i < 4; ++i) wcnt[tid + i * 512] = 0;

    const int k = bid * 512 + tid;
    const float x = dom[k * 3 + 0];
    const float y = dom[k * 3 + 1];
    const float z = dom[k * 3 + 2];
    g_kcoef[k] = make_float4(x, y, z, -LCONST * (x * x + y * y + z * z));
    const int c = cell_of(x, y, z);
    __syncthreads();

    unsigned mm  = __match_any_sync(0xffffffffu, c);
    int     rank = __popc(mm & ((1u << lane) - 1u));
    if (rank == 0) wcnt[w * 128 + c] = __popc(mm);
    __syncthreads();

    if (tid < NCELLS) {
        int acc = 0;
        #pragma unroll
        for (int ww = 0; ww < 16; ++ww) {
            int v = wcnt[ww * 128 + tid];
            wcnt[ww * 128 + tid] = acc;       // exclusive warp base
            acc += v;
        }
        g_dcnt2[tid * NSLICE + bid] = min(acc, SLCAP);
    }
    __syncthreads();

    int slot = wcnt[w * 128 + c] + rank;
    if (slot < SLCAP) g_dslice[(c * NSLICE + bid) * SLCAP + slot] = k;
}

// ---------------------------------------------------------------------------
// prep2: grid (125, 17) x 128 threads. Per (cell, source):
//   load ALL 1024 raw atoms of the source to smem, prune to atoms within
//   RCUT of the home cell cube (dropped terms bounded above), transform to
//   coefficients, pack f32x2 pairs -> global (and smem).
// s==0 blocks additionally stitch the cell's dom points into contiguous
//   (kcoef) arrays and compute theta0 into g_t0c. Slice prefix is an exact
//   32-lane warp shuffle-scan (deterministic integer ops).
// Deterministic: prune preserves atom index order; theta0 inner order fixed.
// ---------------------------------------------------------------------------
__global__ void __launch_bounds__(128) prep2_kernel(const float* __restrict__ C1,
                                                    const float* __restrict__ C) {
    __shared__ float4     satoms[NATOMS];     // raw coords, then compacted
    __shared__ ulonglong2 sA[NPAIR], sB[NPAIR];
    __shared__ float4     skc[DCAP];
    __shared__ int        sNk, sNpts;
    const int cell = blockIdx.x;
    const int s    = blockIdx.y;
    const int tid  = threadIdx.x;
    const int lane = tid & 31;
    const int cx = cell % NC, cy = (cell / NC) % NC, cz = cell / (NC * NC);

    const float* src = (s == 0) ? C : (C1 + (size_t)(s - 1) * NATOMS * 3);
    for (int i = tid; i < NATOMS; i += 128) {
        satoms[i] = make_float4(src[i * 3 + 0], src[i * 3 + 1], src[i * 3 + 2], 0.f);
    }
    __syncthreads();

    // prune (warp 0, deterministic in-place ballot compaction over all atoms)
    if (tid < 32) {
        const float lox = cx * 2.f, hix = lox + 2.f;
        const float loy = cy * 2.f, hiy = loy + 2.f;
        const float loz = cz * 2.f, hiz = loz + 2.f;
        int nk = 0;
        for (int i0 = 0; i0 < NATOMS; i0 += 32) {
            int i = i0 + lane;
            float4 a = satoms[i];
            float dx = fmaxf(fmaxf(lox - a.x, a.x - hix), 0.f);
            float dy = fmaxf(fmaxf(loy - a.y, a.y - hiy), 0.f);
            float dz = fmaxf(fmaxf(loz - a.z, a.z - hiz), 0.f);
            bool keep = fmaf(dx, dx, fmaf(dy, dy, dz * dz)) <= RCUT2;
            unsigned m = __ballot_sync(0xffffffffu, keep);
            __syncwarp();
            if (keep) {
                int pos = nk + __popc(m & ((1u << lane) - 1u));
                if (pos < SCAP) satoms[pos] = a;
            }
            nk += __popc(m);
        }
        if (lane == 0) sNk = min(nk, SCAP);
    }
    __syncthreads();

    const int nk     = sNk;
    const int npairs = (nk + 1) >> 1;

    // pack coefficient pairs (transform raw -> (2Lx,2Ly,2Lz,-L|x|^2) here)
    ulonglong2* gA = g_pairsA + (size_t)(s * NCELLS + cell) * NPAIR;
    ulonglong2* gB = g_pairsB + (size_t)(s * NCELLS + cell) * NPAIR;
    for (int jp = tid; jp < npairs; jp += 128) {
        float4 a = satoms[2 * jp];
        float4 ac = make_float4(2.f * LCONST * a.x, 2.f * LCONST * a.y,
                                2.f * LCONST * a.z,
                                -LCONST * (a.x * a.x + a.y * a.y + a.z * a.z));
        float4 bc;
        if (2 * jp + 1 < nk) {
            float4 b = satoms[2 * jp + 1];
            bc = make_float4(2.f * LCONST * b.x, 2.f * LCONST * b.y,
                             2.f * LCONST * b.z,
                             -LCONST * (b.x * b.x + b.y * b.y + b.z * b.z));
        } else {
            bc = make_float4(0.f, 0.f, 0.f, -1e30f);   // pad -> exp2 flushes to 0
        }
        ulonglong2 pa = make_ulonglong2(pk2(ac.x, bc.x), pk2(ac.y, bc.y));
        ulonglong2 pb = make_ulonglong2(pk2(ac.z, bc.z), pk2(ac.w, bc.w));
        gA[jp] = pa;  gB[jp] = pb;
        sA[jp] = pa;  sB[jp] = pb;
    }
    if (tid == 0) g_pcount[s * NCELLS + cell] = npairs;

    if (s == 0) {
        // stitch dom points (deterministic order) into smem + global
        __shared__ int soff[NSLICE + 1];
        if (tid < 32) {
            int cnt = g_dcnt2[cell * NSLICE + tid];
            int x = cnt;
            #pragma unroll
            for (int st = 1; st < 32; st <<= 1) {
                int y = __shfl_up_sync(0xffffffffu, x, st);
                if (lane >= st) x += y;
            }
            soff[tid] = x - cnt;              // exclusive prefix
            if (tid == 31) {
                soff[32] = x;
                g_dcountc[cell] = x;
                sNpts = x;
            }
        }
        __syncthreads();
        for (int idx = tid; idx < NSLICE * SLCAP; idx += 128) {
            int sl = idx / SLCAP, j = idx % SLCAP;
            if (j < soff[sl + 1] - soff[sl]) {
                int k = g_dslice[(cell * NSLICE + sl) * SLCAP + j];
                int pos = soff[sl] + j;
                float4 kc = g_kcoef[k];
                skc[pos] = kc;
                g_kc[cell * DCAP + pos] = kc;
            }
        }
        __syncthreads();

        // theta0 for this cell's points (fixed order)
        const int npts = sNpts;
        for (int p = tid; p < npts; p += 128) {
            g_t0c[cell * DCAP + p] = theta_point(skc[p], sA, sB, npairs);
        }
    }
}

// ---------------------------------------------------------------------------
// thetaB: grid (125, 16) x 160 threads, s = b+1. Computes theta_b per point,
// multiplies by theta0 (stitched order) immediately, block-reduces to one
// partial per (b, cell). The LAST block per b (elected by atomic counter)
// folds all 125 partials IN FIXED ORDER and writes out[b], then resets the
// counter for graph replay. Deterministic: the atomic elects only WHO folds;
// the fold order is fixed.
// scale = A*V/sqrt(n1*n2) = 8 * (1000/16384) / 1024.
// ---------------------------------------------------------------------------
__global__ void __launch_bounds__(160) thetaB_kernel(float* __restrict__ out) {
    __shared__ ulonglong2 sA[NPAIR];
    __shared__ ulonglong2 sB[NPAIR];
    __shared__ float      red[5];
    __shared__ int        sIsLast;
    const int cell = blockIdx.x;
    const int b    = blockIdx.y;
    const int s    = b + 1;
    const int tid  = threadIdx.x;
    const int lane = tid & 31;
    const int w    = tid >> 5;

    const int npairs = g_pcount[s * NCELLS + cell];
    const int npts   = g_dcountc[cell];
    const ulonglong2* gA = g_pairsA + (size_t)(s * NCELLS + cell) * NPAIR;
    const ulonglong2* gB = g_pairsB + (size_t)(s * NCELLS + cell) * NPAIR;
    for (int i = tid; i < npairs; i += 160) {
        sA[i] = gA[i];
        sB[i] = gB[i];
    }
    __syncthreads();

    float pdot = 0.f;
    for (int p = tid; p < npts; p += 160) {
        float tb = theta_point(g_kc[cell * DCAP + p], sA, sB, npairs);
        pdot += tb * g_t0c[cell * DCAP + p];
    }
    #pragma unroll
    for (int st = 16; st > 0; st >>= 1)
        pdot += __shfl_down_sync(0xffffffffu, pdot, st);
    if (lane == 0) red[w] = pdot;
    __syncthreads();
    if (tid == 0) {
        float a = 0.f;
        #pragma unroll
        for (int i = 0; i < 5; ++i) a += red[i];
        g_part[b * NCELLS + cell] = a;
        __threadfence();
        int old = atomicAdd(&g_ctr[b], 1);
        sIsLast = (old == NCELLS - 1);
    }
    __syncthreads();

    if (sIsLast) {
        __threadfence();
        // fold 125 partials in fixed order (warps 0..3, lanes ascending)
        float v = (tid < NCELLS) ? ldcg(&g_part[b * NCELLS + tid]) : 0.f;
        #pragma unroll
        for (int st = 16; st > 0; st >>= 1)
            v += __shfl_down_sync(0xffffffffu, v, st);
        if (lane == 0) red[w] = v;
        __syncthreads();
        if (tid == 0) {
            float a = ((red[0] + red[1]) + (red[2] + red[3])) + red[4];
            float dot = 4.76837158203125e-4f * a;
            dot = fminf(fmaxf(dot, 0.f), 1.f);
            out[b] = 1.f - dot;
            g_ctr[b] = 0;                    // reset for graph replay
        }
    }
}

extern "C" void kernel_launch(void* const* d_in, const int* in_sizes, int n_in,
                              void* d_out, int out_size) {
    const float* C1  = (const float*)d_in[0];   // (16, 1024, 3)
    const float* C   = (const float*)d_in[1];   // (1024, 3)
    const float* dom = (const float*)d_in[2];   // (16384, 3)

    prep1_kernel<<<NSLICE, 512>>>(dom);
    prep2_kernel<<<dim3(NCELLS, NSRC), 128>>>(C1, C);
    thetaB_kernel<<<dim3(NCELLS, NB), 160>>>((float*)d_out);
}